// round 1
// baseline (speedup 1.0000x reference)
#include <cuda_runtime.h>
#include <math.h>

// Problem constants (fixed shapes from reference)
#define B_   8
#define N_   2048
#define M_   512
#define C_   256
#define NR_  4
#define CNT_ (B_*NR_*N_)      // 65536 elements per channel for BN stats

// ---------------- scratch (static device globals; no allocation) ----------------
__device__ float g_G [B_*NR_*M_*C_];   // [z=b*4+r][m][o]  16.8 MB
__device__ float g_y1[B_*NR_*C_*N_];   // [z][c][n]        67 MB
__device__ int   g_idx[B_*N_*3];
__device__ float g_w  [B_*N_*3];
__device__ float g_s1[C_], g_q1[C_], g_s2[C_], g_q2[C_];
__device__ float g_scale1[C_], g_bias1[C_], g_scale2[C_], g_bias2[C_];

// ---------------- kernel 0: zero BN accumulators (graph replays!) ----------------
__global__ void zero_stats_kernel() {
    int t = threadIdx.x;
    g_s1[t] = 0.f; g_q1[t] = 0.f; g_s2[t] = 0.f; g_q2[t] = 0.f;
}

// ---------------- kernel 1: 3-NN + inverse-distance weights ----------------
__global__ void knn_kernel(const float* __restrict__ unknown,
                           const float* __restrict__ known) {
    __shared__ float ks[M_*3];
    int b = blockIdx.y;
    const float* kb = known + (size_t)b * M_ * 3;
    for (int i = threadIdx.x; i < M_*3; i += blockDim.x) ks[i] = kb[i];
    __syncthreads();

    int n = blockIdx.x * blockDim.x + threadIdx.x;
    const float* u = unknown + ((size_t)b * N_ + n) * 3;
    float ux = u[0], uy = u[1], uz = u[2];

    float d0 = 3.4e38f, d1 = 3.4e38f, d2 = 3.4e38f;
    int   i0 = 0, i1 = 0, i2 = 0;
    for (int m = 0; m < M_; m++) {
        float dx = ux - ks[m*3], dy = uy - ks[m*3+1], dz = uz - ks[m*3+2];
        float d  = dx*dx + dy*dy + dz*dz;
        if (d < d2) {
            if (d < d0)      { d2=d1; i2=i1; d1=d0; i1=i0; d0=d; i0=m; }
            else if (d < d1) { d2=d1; i2=i1; d1=d;  i1=m; }
            else             { d2=d;  i2=m; }
        }
    }
    float r0 = 1.f / (sqrtf(fmaxf(d0, 0.f)) + 1e-8f);
    float r1 = 1.f / (sqrtf(fmaxf(d1, 0.f)) + 1e-8f);
    float r2 = 1.f / (sqrtf(fmaxf(d2, 0.f)) + 1e-8f);
    float inv = 1.f / (r0 + r1 + r2);
    int base = (b * N_ + n) * 3;
    g_idx[base] = i0; g_idx[base+1] = i1; g_idx[base+2] = i2;
    g_w[base] = r0*inv; g_w[base+1] = r1*inv; g_w[base+2] = r2*inv;
}

// ---------------- kernel 2: G[z][m][o] = sum_c W1a[o][c] * kf[b][c][r][m] ----------------
// tile: 64(m) x 64(o) x 16(c); 256 threads; 4x4 per thread
__global__ __launch_bounds__(256) void gemmG_kernel(const float* __restrict__ kf,
                                                    const float* __restrict__ W1) {
    int z = blockIdx.z; int b = z >> 2; int r = z & 3;
    int m0 = blockIdx.y * 64, o0 = blockIdx.x * 64;
    __shared__ float As[16][64];   // [c][m]
    __shared__ float Bs[16][68];   // [c][o] (padded, rows 16B-aligned)

    const float* kfb = kf + (size_t)b * (C_*NR_*M_) + (size_t)r * M_;
    int tid = threadIdx.x;
    int tm = tid >> 4, to = tid & 15;           // compute mapping
    int lAc = tid >> 4, lAm = (tid & 15) * 4;   // As load
    int lBo = tid >> 2, lBc = (tid & 3) * 4;    // Bs load

    float acc[4][4] = {};
    for (int c0 = 0; c0 < C_; c0 += 16) {
        float4 av = *(const float4*)(kfb + (size_t)(c0 + lAc) * (NR_*M_) + m0 + lAm);
        float4 bv = *(const float4*)(W1 + (size_t)(o0 + lBo) * 512 + c0 + lBc);
        __syncthreads();
        *(float4*)&As[lAc][lAm] = av;
        Bs[lBc  ][lBo] = bv.x; Bs[lBc+1][lBo] = bv.y;
        Bs[lBc+2][lBo] = bv.z; Bs[lBc+3][lBo] = bv.w;
        __syncthreads();
        #pragma unroll
        for (int k = 0; k < 16; k++) {
            float4 a = *(const float4*)&As[k][tm*4];
            float4 p = *(const float4*)&Bs[k][to*4];
            float ar[4] = {a.x,a.y,a.z,a.w};
            float br[4] = {p.x,p.y,p.z,p.w};
            #pragma unroll
            for (int i = 0; i < 4; i++)
                #pragma unroll
                for (int j = 0; j < 4; j++)
                    acc[i][j] = fmaf(ar[i], br[j], acc[i][j]);
        }
    }
    float* Gz = g_G + (size_t)z * M_ * C_;
    #pragma unroll
    for (int i = 0; i < 4; i++) {
        *(float4*)(Gz + (size_t)(m0 + tm*4 + i) * C_ + o0 + to*4) =
            make_float4(acc[i][0], acc[i][1], acc[i][2], acc[i][3]);
    }
}

// ---------------- kernel 3: y1[z][o][n] = W1b @ uf + gather(G, idx, w); BN1 stats ----------------
// tile: 64(o) x 128(n) x 16(c); 256 threads; 4x8 per thread
__global__ __launch_bounds__(256) void gemmY1_kernel(const float* __restrict__ uf,
                                                     const float* __restrict__ W1) {
    int z = blockIdx.z; int b = z >> 2; int r = z & 3;
    int o0 = blockIdx.y * 64, n0 = blockIdx.x * 128;
    __shared__ float As[16][68];    // [c][o]
    __shared__ float Bs[16][128];   // [c][n]
    __shared__ float s_w[384];
    __shared__ int   s_i[384];
    __shared__ float s_sum[64], s_sq[64];

    int tid = threadIdx.x;
    for (int l = tid; l < 384; l += 256) {
        s_w[l] = g_w[(b * N_ + n0) * 3 + l];
        s_i[l] = g_idx[(b * N_ + n0) * 3 + l];
    }

    const float* ufb = uf + (size_t)b * (C_*NR_*N_) + (size_t)r * N_;
    int to = tid >> 4, tn = tid & 15;           // compute mapping
    int lAo = tid >> 2, lAc = (tid & 3) * 4;    // As load
    int lBc = tid >> 4, lBn = (tid & 15) * 8;   // Bs load

    float acc[4][8] = {};
    for (int c0 = 0; c0 < C_; c0 += 16) {
        float4 av = *(const float4*)(W1 + (size_t)(o0 + lAo) * 512 + 256 + c0 + lAc);
        const float* src = ufb + (size_t)(c0 + lBc) * (NR_*N_) + n0 + lBn;
        float4 bv0 = *(const float4*)src;
        float4 bv1 = *(const float4*)(src + 4);
        __syncthreads();
        As[lAc  ][lAo] = av.x; As[lAc+1][lAo] = av.y;
        As[lAc+2][lAo] = av.z; As[lAc+3][lAo] = av.w;
        *(float4*)&Bs[lBc][lBn]     = bv0;
        *(float4*)&Bs[lBc][lBn + 4] = bv1;
        __syncthreads();
        #pragma unroll
        for (int k = 0; k < 16; k++) {
            float4 a = *(const float4*)&As[k][to*4];
            float4 p = *(const float4*)&Bs[k][tn*8];
            float4 q = *(const float4*)&Bs[k][tn*8 + 4];
            float ar[4] = {a.x,a.y,a.z,a.w};
            float br[8] = {p.x,p.y,p.z,p.w,q.x,q.y,q.z,q.w};
            #pragma unroll
            for (int i = 0; i < 4; i++)
                #pragma unroll
                for (int j = 0; j < 8; j++)
                    acc[i][j] = fmaf(ar[i], br[j], acc[i][j]);
        }
    }

    // --- gather epilogue: += sum_j w_j * G[z][idx_j][o] (G hot in L2) ---
    const float* Gz = g_G + (size_t)z * M_ * C_;
    #pragma unroll
    for (int j = 0; j < 8; j++) {
        int nl = tn*8 + j;
        float w0 = s_w[nl*3], w1 = s_w[nl*3+1], w2 = s_w[nl*3+2];
        int   m0i = s_i[nl*3], m1i = s_i[nl*3+1], m2i = s_i[nl*3+2];
        float4 gA = *(const float4*)(Gz + (size_t)m0i * C_ + o0 + to*4);
        float4 gB = *(const float4*)(Gz + (size_t)m1i * C_ + o0 + to*4);
        float4 gC = *(const float4*)(Gz + (size_t)m2i * C_ + o0 + to*4);
        acc[0][j] += w0*gA.x + w1*gB.x + w2*gC.x;
        acc[1][j] += w0*gA.y + w1*gB.y + w2*gC.y;
        acc[2][j] += w0*gA.z + w1*gB.z + w2*gC.z;
        acc[3][j] += w0*gA.w + w1*gB.w + w2*gC.w;
    }

    // --- BN1 stats + write y1 ---
    __syncthreads();
    if (tid < 64) { s_sum[tid] = 0.f; s_sq[tid] = 0.f; }
    __syncthreads();
    float* y1z = g_y1 + (size_t)z * C_ * N_;
    #pragma unroll
    for (int i = 0; i < 4; i++) {
        float ps = 0.f, pq = 0.f;
        #pragma unroll
        for (int j = 0; j < 8; j++) { float v = acc[i][j]; ps += v; pq += v*v; }
        atomicAdd(&s_sum[to*4 + i], ps);
        atomicAdd(&s_sq [to*4 + i], pq);
        float* dst = y1z + (size_t)(o0 + to*4 + i) * N_ + n0 + tn*8;
        *(float4*)dst       = make_float4(acc[i][0], acc[i][1], acc[i][2], acc[i][3]);
        *(float4*)(dst + 4) = make_float4(acc[i][4], acc[i][5], acc[i][6], acc[i][7]);
    }
    __syncthreads();
    if (tid < 64) {
        atomicAdd(&g_s1[o0 + tid], s_sum[tid]);
        atomicAdd(&g_q1[o0 + tid], s_sq[tid]);
    }
}

// ---------------- kernel 4/6: BN finalize ----------------
__global__ void bnfin_kernel(const float* __restrict__ gamma,
                             const float* __restrict__ beta, int which) {
    int t = threadIdx.x;
    float s = which ? g_s2[t] : g_s1[t];
    float q = which ? g_q2[t] : g_q1[t];
    float mean = s * (1.f / CNT_);
    float var  = q * (1.f / CNT_) - mean * mean;
    float sc = gamma[t] * rsqrtf(var + 1e-5f);
    float bi = beta[t] - mean * sc;
    if (which) { g_scale2[t] = sc; g_bias2[t] = bi; }
    else       { g_scale1[t] = sc; g_bias1[t] = bi; }
}

// ---------------- kernel 5: z = W2 @ relu(bn1(y1)) -> d_out; BN2 stats ----------------
__global__ __launch_bounds__(256) void gemmZ_kernel(const float* __restrict__ W2,
                                                    float* __restrict__ out) {
    int z = blockIdx.z; int b = z >> 2; int r = z & 3;
    int o0 = blockIdx.y * 64, n0 = blockIdx.x * 128;
    __shared__ float As[16][68];
    __shared__ float Bs[16][128];
    __shared__ float s_sum[64], s_sq[64];

    int tid = threadIdx.x;
    const float* y1z = g_y1 + (size_t)z * C_ * N_;
    int to = tid >> 4, tn = tid & 15;
    int lAo = tid >> 2, lAc = (tid & 3) * 4;
    int lBc = tid >> 4, lBn = (tid & 15) * 8;

    float acc[4][8] = {};
    for (int c0 = 0; c0 < C_; c0 += 16) {
        float4 av = *(const float4*)(W2 + (size_t)(o0 + lAo) * 256 + c0 + lAc);
        const float* src = y1z + (size_t)(c0 + lBc) * N_ + n0 + lBn;
        float4 bv0 = *(const float4*)src;
        float4 bv1 = *(const float4*)(src + 4);
        float sc = g_scale1[c0 + lBc], bi = g_bias1[c0 + lBc];
        bv0.x = fmaxf(fmaf(bv0.x, sc, bi), 0.f); bv0.y = fmaxf(fmaf(bv0.y, sc, bi), 0.f);
        bv0.z = fmaxf(fmaf(bv0.z, sc, bi), 0.f); bv0.w = fmaxf(fmaf(bv0.w, sc, bi), 0.f);
        bv1.x = fmaxf(fmaf(bv1.x, sc, bi), 0.f); bv1.y = fmaxf(fmaf(bv1.y, sc, bi), 0.f);
        bv1.z = fmaxf(fmaf(bv1.z, sc, bi), 0.f); bv1.w = fmaxf(fmaf(bv1.w, sc, bi), 0.f);
        __syncthreads();
        As[lAc  ][lAo] = av.x; As[lAc+1][lAo] = av.y;
        As[lAc+2][lAo] = av.z; As[lAc+3][lAo] = av.w;
        *(float4*)&Bs[lBc][lBn]     = bv0;
        *(float4*)&Bs[lBc][lBn + 4] = bv1;
        __syncthreads();
        #pragma unroll
        for (int k = 0; k < 16; k++) {
            float4 a = *(const float4*)&As[k][to*4];
            float4 p = *(const float4*)&Bs[k][tn*8];
            float4 q = *(const float4*)&Bs[k][tn*8 + 4];
            float ar[4] = {a.x,a.y,a.z,a.w};
            float br[8] = {p.x,p.y,p.z,p.w,q.x,q.y,q.z,q.w};
            #pragma unroll
            for (int i = 0; i < 4; i++)
                #pragma unroll
                for (int j = 0; j < 8; j++)
                    acc[i][j] = fmaf(ar[i], br[j], acc[i][j]);
        }
    }

    __syncthreads();
    if (tid < 64) { s_sum[tid] = 0.f; s_sq[tid] = 0.f; }
    __syncthreads();
    // out layout: ((b*256 + o)*4 + r)*2048 + n
    float* ob = out + (size_t)b * (256*NR_*N_) + (size_t)r * N_;
    #pragma unroll
    for (int i = 0; i < 4; i++) {
        float ps = 0.f, pq = 0.f;
        #pragma unroll
        for (int j = 0; j < 8; j++) { float v = acc[i][j]; ps += v; pq += v*v; }
        atomicAdd(&s_sum[to*4 + i], ps);
        atomicAdd(&s_sq [to*4 + i], pq);
        float* dst = ob + (size_t)(o0 + to*4 + i) * (NR_*N_) + n0 + tn*8;
        *(float4*)dst       = make_float4(acc[i][0], acc[i][1], acc[i][2], acc[i][3]);
        *(float4*)(dst + 4) = make_float4(acc[i][4], acc[i][5], acc[i][6], acc[i][7]);
    }
    __syncthreads();
    if (tid < 64) {
        atomicAdd(&g_s2[o0 + tid], s_sum[tid]);
        atomicAdd(&g_q2[o0 + tid], s_sq[tid]);
    }
}

// ---------------- kernel 7: in-place BN2 + ReLU on d_out ----------------
__global__ void out_kernel(float* __restrict__ out) {
    int i = blockIdx.x * blockDim.x + threadIdx.x;    // float4 index
    int o = (i >> 11) & 255;                          // (i*4 / 8192) % 256
    float sc = g_scale2[o], bi = g_bias2[o];
    float4 v = ((float4*)out)[i];
    v.x = fmaxf(fmaf(v.x, sc, bi), 0.f);
    v.y = fmaxf(fmaf(v.y, sc, bi), 0.f);
    v.z = fmaxf(fmaf(v.z, sc, bi), 0.f);
    v.w = fmaxf(fmaf(v.w, sc, bi), 0.f);
    ((float4*)out)[i] = v;
}

// ---------------- launch ----------------
extern "C" void kernel_launch(void* const* d_in, const int* in_sizes, int n_in,
                              void* d_out, int out_size) {
    const float* unknown = (const float*)d_in[0];
    const float* known   = (const float*)d_in[1];
    const float* uf      = (const float*)d_in[2];
    const float* kf      = (const float*)d_in[3];
    const float* W1      = (const float*)d_in[4];
    const float* g1      = (const float*)d_in[5];
    const float* b1      = (const float*)d_in[6];
    const float* W2      = (const float*)d_in[7];
    const float* g2      = (const float*)d_in[8];
    const float* b2      = (const float*)d_in[9];
    float* out = (float*)d_out;

    zero_stats_kernel<<<1, 256>>>();
    knn_kernel<<<dim3(N_/256, B_), 256>>>(unknown, known);
    gemmG_kernel<<<dim3(C_/64, M_/64, B_*NR_), 256>>>(kf, W1);
    gemmY1_kernel<<<dim3(N_/128, C_/64, B_*NR_), 256>>>(uf, W1);
    bnfin_kernel<<<1, 256>>>(g1, b1, 0);
    gemmZ_kernel<<<dim3(N_/128, C_/64, B_*NR_), 256>>>(W2, out);
    bnfin_kernel<<<1, 256>>>(g2, b2, 1);
    out_kernel<<<(B_*256*NR_*N_/4) / 256, 256>>>(out);
}

// round 3
// speedup vs baseline: 2.4377x; 2.4377x over previous
#include <cuda_runtime.h>
#include <math.h>

// Problem constants (fixed shapes from reference)
#define B_   8
#define N_   2048
#define M_   512
#define C_   256
#define NR_  4
#define CNT_ (B_*NR_*N_)      // 65536 elements per channel for BN stats

// ---------------- scratch (static device globals; no allocation) ----------------
__device__ float g_G [B_*NR_*M_*C_];   // [z=b*4+r][m][o]  16.8 MB
__device__ float g_y1[B_*NR_*C_*N_];   // [z][c][n]        67 MB
__device__ int   g_idx[B_*N_*3];
__device__ float g_w  [B_*N_*3];
__device__ float g_s1[C_], g_q1[C_], g_s2[C_], g_q2[C_];
__device__ float g_scale1[C_], g_bias1[C_], g_scale2[C_], g_bias2[C_];

// ---------------- tf32 helpers ----------------
__device__ __forceinline__ unsigned f2tf(float f) {
    unsigned u; asm("cvt.rna.tf32.f32 %0, %1;" : "=r"(u) : "f"(f)); return u;
}
__device__ __forceinline__ void mma8(float* c, const unsigned* a, const unsigned* b) {
    asm volatile("mma.sync.aligned.m16n8k8.row.col.f32.tf32.tf32.f32 "
        "{%0,%1,%2,%3}, {%4,%5,%6,%7}, {%8,%9}, {%0,%1,%2,%3};"
        : "+f"(c[0]), "+f"(c[1]), "+f"(c[2]), "+f"(c[3])
        : "r"(a[0]), "r"(a[1]), "r"(a[2]), "r"(a[3]), "r"(b[0]), "r"(b[1]));
}

// ---------------- kernel 0: zero BN accumulators (graph replays!) ----------------
__global__ void zero_stats_kernel() {
    int t = threadIdx.x;
    g_s1[t] = 0.f; g_q1[t] = 0.f; g_s2[t] = 0.f; g_q2[t] = 0.f;
}

// ---------------- kernel 1: 3-NN + inverse-distance weights ----------------
__global__ void knn_kernel(const float* __restrict__ unknown,
                           const float* __restrict__ known) {
    __shared__ float ks[M_*3];
    int b = blockIdx.y;
    const float* kb = known + (size_t)b * M_ * 3;
    for (int i = threadIdx.x; i < M_*3; i += blockDim.x) ks[i] = kb[i];
    __syncthreads();

    int n = blockIdx.x * blockDim.x + threadIdx.x;
    const float* u = unknown + ((size_t)b * N_ + n) * 3;
    float ux = u[0], uy = u[1], uz = u[2];

    float d0 = 3.4e38f, d1 = 3.4e38f, d2 = 3.4e38f;
    int   i0 = 0, i1 = 0, i2 = 0;
    for (int m = 0; m < M_; m++) {
        float dx = ux - ks[m*3], dy = uy - ks[m*3+1], dz = uz - ks[m*3+2];
        float d  = dx*dx + dy*dy + dz*dz;
        if (d < d2) {
            if (d < d0)      { d2=d1; i2=i1; d1=d0; i1=i0; d0=d; i0=m; }
            else if (d < d1) { d2=d1; i2=i1; d1=d;  i1=m; }
            else             { d2=d;  i2=m; }
        }
    }
    float r0 = 1.f / (sqrtf(fmaxf(d0, 0.f)) + 1e-8f);
    float r1 = 1.f / (sqrtf(fmaxf(d1, 0.f)) + 1e-8f);
    float r2 = 1.f / (sqrtf(fmaxf(d2, 0.f)) + 1e-8f);
    float inv = 1.f / (r0 + r1 + r2);
    int base = (b * N_ + n) * 3;
    g_idx[base] = i0; g_idx[base+1] = i1; g_idx[base+2] = i2;
    g_w[base] = r0*inv; g_w[base+1] = r1*inv; g_w[base+2] = r2*inv;
}

// ============================================================================
// tf32 MMA GEMM core: block tile 128 (o = mma-M) x 64 (n = mma-N), K chunk 16.
// 8 warps as (4 o) x (2 n); warp tile 32o x 32n = 2 mtiles x 4 ntiles m16n8k8.
// A = weights W[o][k] staged as ws[k][o] (pitch 136 -> conflict-free frag LDS).
// B = activations x[k][n] staged as xs[k][n] (pitch 72).
// Result staged to Ys[n][o] (pitch 132) for flexible epilogues.
// ============================================================================

// ---------------- kernel 2: G[z][m][o] = W1a @ kf ----------------
__global__ __launch_bounds__(256) void gemmG_kernel(const float* __restrict__ kf,
                                                    const float* __restrict__ W1) {
    int z = blockIdx.z, b = z >> 2, r = z & 3;
    int o0 = blockIdx.y * 128, n0 = blockIdx.x * 64;   // n == m dim here
    __shared__ unsigned ws[16][136];
    __shared__ unsigned xs[16][72];
    __shared__ float Ys[64][132];

    const float* kfb = kf + (size_t)b * (C_*NR_*M_) + (size_t)r * M_;
    int tid = threadIdx.x, lane = tid & 31, wp = tid >> 5;
    int wo = wp >> 1, wn = wp & 1, g = lane >> 2, t = lane & 3;
    int lwo = tid >> 2, lwk = (tid & 3) * 4;
    int xk = tid >> 4, xq = (tid & 15) * 4;

    float acc[2][4][4] = {};
    for (int c0 = 0; c0 < C_; c0 += 16) {
        float4 wv0 = *(const float4*)(W1 + (size_t)(o0 + lwo) * 512 + c0 + lwk);
        float4 wv1 = *(const float4*)(W1 + (size_t)(o0 + 64 + lwo) * 512 + c0 + lwk);
        float4 xv  = *(const float4*)(kfb + (size_t)(c0 + xk) * (NR_*M_) + n0 + xq);
        __syncthreads();
        ws[lwk+0][lwo] = f2tf(wv0.x); ws[lwk+1][lwo] = f2tf(wv0.y);
        ws[lwk+2][lwo] = f2tf(wv0.z); ws[lwk+3][lwo] = f2tf(wv0.w);
        ws[lwk+0][64+lwo] = f2tf(wv1.x); ws[lwk+1][64+lwo] = f2tf(wv1.y);
        ws[lwk+2][64+lwo] = f2tf(wv1.z); ws[lwk+3][64+lwo] = f2tf(wv1.w);
        uint4 xb = make_uint4(f2tf(xv.x), f2tf(xv.y), f2tf(xv.z), f2tf(xv.w));
        *(uint4*)&xs[xk][xq] = xb;
        __syncthreads();
        #pragma unroll
        for (int ks = 0; ks < 16; ks += 8) {
            unsigned af[2][4], bf[4][2];
            #pragma unroll
            for (int mi = 0; mi < 2; mi++) {
                int ob = wo*32 + mi*16;
                af[mi][0] = ws[ks+t][ob+g];   af[mi][1] = ws[ks+t][ob+g+8];
                af[mi][2] = ws[ks+t+4][ob+g]; af[mi][3] = ws[ks+t+4][ob+g+8];
            }
            #pragma unroll
            for (int ni = 0; ni < 4; ni++) {
                int nb = wn*32 + ni*8;
                bf[ni][0] = xs[ks+t][nb+g];   bf[ni][1] = xs[ks+t+4][nb+g];
            }
            #pragma unroll
            for (int mi = 0; mi < 2; mi++)
                #pragma unroll
                for (int ni = 0; ni < 4; ni++)
                    mma8(acc[mi][ni], af[mi], bf[ni]);
        }
    }
    __syncthreads();
    #pragma unroll
    for (int mi = 0; mi < 2; mi++)
        #pragma unroll
        for (int ni = 0; ni < 4; ni++) {
            int orow = wo*32 + mi*16 + g;
            int ncol = wn*32 + ni*8 + 2*t;
            Ys[ncol  ][orow  ] = acc[mi][ni][0];
            Ys[ncol+1][orow  ] = acc[mi][ni][1];
            Ys[ncol  ][orow+8] = acc[mi][ni][2];
            Ys[ncol+1][orow+8] = acc[mi][ni][3];
        }
    __syncthreads();
    // coalesced copy to G[z][m][o] (o contiguous, float4)
    float* Gz = g_G + (size_t)z * M_ * C_;
    int oq = tid & 31, nl0 = tid >> 5;
    #pragma unroll
    for (int it = 0; it < 8; it++) {
        int nl = nl0 + it*8;
        float4 v = *(float4*)&Ys[nl][oq*4];
        *(float4*)(Gz + (size_t)(n0 + nl) * C_ + o0 + oq*4) = v;
    }
}

// ---------------- kernel 3: y1 = W1b @ uf + gather(G, idx, w); BN1 stats ----------------
__global__ __launch_bounds__(256) void gemmY1_kernel(const float* __restrict__ uf,
                                                     const float* __restrict__ W1) {
    int z = blockIdx.z, b = z >> 2, r = z & 3;
    int o0 = blockIdx.y * 128, n0 = blockIdx.x * 64;
    __shared__ union {
        struct { unsigned ws[16][136]; unsigned xs[16][72]; } mm;
        struct { float w[192]; int idx[192]; float s[128]; float q[128]; } ep;
    } S;
    __shared__ float Ys[64][132];

    const float* ufb = uf + (size_t)b * (C_*NR_*N_) + (size_t)r * N_;
    int tid = threadIdx.x, lane = tid & 31, wp = tid >> 5;
    int wo = wp >> 1, wn = wp & 1, g = lane >> 2, t = lane & 3;
    int lwo = tid >> 2, lwk = (tid & 3) * 4;
    int xk = tid >> 4, xq = (tid & 15) * 4;

    float acc[2][4][4] = {};
    for (int c0 = 0; c0 < C_; c0 += 16) {
        float4 wv0 = *(const float4*)(W1 + (size_t)(o0 + lwo) * 512 + 256 + c0 + lwk);
        float4 wv1 = *(const float4*)(W1 + (size_t)(o0 + 64 + lwo) * 512 + 256 + c0 + lwk);
        float4 xv  = *(const float4*)(ufb + (size_t)(c0 + xk) * (NR_*N_) + n0 + xq);
        __syncthreads();
        S.mm.ws[lwk+0][lwo] = f2tf(wv0.x); S.mm.ws[lwk+1][lwo] = f2tf(wv0.y);
        S.mm.ws[lwk+2][lwo] = f2tf(wv0.z); S.mm.ws[lwk+3][lwo] = f2tf(wv0.w);
        S.mm.ws[lwk+0][64+lwo] = f2tf(wv1.x); S.mm.ws[lwk+1][64+lwo] = f2tf(wv1.y);
        S.mm.ws[lwk+2][64+lwo] = f2tf(wv1.z); S.mm.ws[lwk+3][64+lwo] = f2tf(wv1.w);
        uint4 xb = make_uint4(f2tf(xv.x), f2tf(xv.y), f2tf(xv.z), f2tf(xv.w));
        *(uint4*)&S.mm.xs[xk][xq] = xb;
        __syncthreads();
        #pragma unroll
        for (int ks = 0; ks < 16; ks += 8) {
            unsigned af[2][4], bf[4][2];
            #pragma unroll
            for (int mi = 0; mi < 2; mi++) {
                int ob = wo*32 + mi*16;
                af[mi][0] = S.mm.ws[ks+t][ob+g];   af[mi][1] = S.mm.ws[ks+t][ob+g+8];
                af[mi][2] = S.mm.ws[ks+t+4][ob+g]; af[mi][3] = S.mm.ws[ks+t+4][ob+g+8];
            }
            #pragma unroll
            for (int ni = 0; ni < 4; ni++) {
                int nb = wn*32 + ni*8;
                bf[ni][0] = S.mm.xs[ks+t][nb+g];   bf[ni][1] = S.mm.xs[ks+t+4][nb+g];
            }
            #pragma unroll
            for (int mi = 0; mi < 2; mi++)
                #pragma unroll
                for (int ni = 0; ni < 4; ni++)
                    mma8(acc[mi][ni], af[mi], bf[ni]);
        }
    }
    __syncthreads();  // ws/xs dead beyond here; ep union becomes live
    // stage accumulators
    #pragma unroll
    for (int mi = 0; mi < 2; mi++)
        #pragma unroll
        for (int ni = 0; ni < 4; ni++) {
            int orow = wo*32 + mi*16 + g;
            int ncol = wn*32 + ni*8 + 2*t;
            Ys[ncol  ][orow  ] = acc[mi][ni][0];
            Ys[ncol+1][orow  ] = acc[mi][ni][1];
            Ys[ncol  ][orow+8] = acc[mi][ni][2];
            Ys[ncol+1][orow+8] = acc[mi][ni][3];
        }
    // load interpolation weights/indices for this n-range; zero stats
    for (int l = tid; l < 192; l += 256) {
        S.ep.w[l]   = g_w  [(b * N_ + n0) * 3 + l];
        S.ep.idx[l] = g_idx[(b * N_ + n0) * 3 + l];
    }
    if (tid < 128) { S.ep.s[tid] = 0.f; S.ep.q[tid] = 0.f; }
    __syncthreads();
    // phase 2: gather epilogue, o-vectorized (G z-slice is L2-hot)
    const float* Gz = g_G + (size_t)z * M_ * C_;
    int oq = tid & 31, nl0 = tid >> 5;
    #pragma unroll
    for (int it = 0; it < 8; it++) {
        int nl = nl0 + it*8;
        float4 v = *(float4*)&Ys[nl][oq*4];
        float w0 = S.ep.w[nl*3], w1 = S.ep.w[nl*3+1], w2 = S.ep.w[nl*3+2];
        int   i0 = S.ep.idx[nl*3], i1 = S.ep.idx[nl*3+1], i2 = S.ep.idx[nl*3+2];
        float4 gA = *(const float4*)(Gz + (size_t)i0 * C_ + o0 + oq*4);
        float4 gB = *(const float4*)(Gz + (size_t)i1 * C_ + o0 + oq*4);
        float4 gC = *(const float4*)(Gz + (size_t)i2 * C_ + o0 + oq*4);
        v.x += w0*gA.x + w1*gB.x + w2*gC.x;
        v.y += w0*gA.y + w1*gB.y + w2*gC.y;
        v.z += w0*gA.z + w1*gB.z + w2*gC.z;
        v.w += w0*gA.w + w1*gB.w + w2*gC.w;
        *(float4*)&Ys[nl][oq*4] = v;
    }
    __syncthreads();
    // phase 3: BN1 stats + coalesced float4 store (n contiguous)
    float* y1z = g_y1 + (size_t)z * C_ * N_;
    int o = tid >> 1, hf = tid & 1;
    float ps = 0.f, pq = 0.f;
    #pragma unroll
    for (int j = 0; j < 8; j++) {
        int n = hf*32 + j*4;
        float4 v = make_float4(Ys[n][o], Ys[n+1][o], Ys[n+2][o], Ys[n+3][o]);
        ps += v.x + v.y + v.z + v.w;
        pq += v.x*v.x + v.y*v.y + v.z*v.z + v.w*v.w;
        *(float4*)(y1z + (size_t)(o0 + o) * N_ + n0 + n) = v;
    }
    atomicAdd(&S.ep.s[o], ps);
    atomicAdd(&S.ep.q[o], pq);
    __syncthreads();
    if (tid < 128) {
        atomicAdd(&g_s1[o0 + tid], S.ep.s[tid]);
        atomicAdd(&g_q1[o0 + tid], S.ep.q[tid]);
    }
}

// ---------------- kernel 4/6: BN finalize ----------------
__global__ void bnfin_kernel(const float* __restrict__ gamma,
                             const float* __restrict__ beta, int which) {
    int t = threadIdx.x;
    float s = which ? g_s2[t] : g_s1[t];
    float q = which ? g_q2[t] : g_q1[t];
    float mean = s * (1.f / CNT_);
    float var  = q * (1.f / CNT_) - mean * mean;
    float sc = gamma[t] * rsqrtf(var + 1e-5f);
    float bi = beta[t] - mean * sc;
    if (which) { g_scale2[t] = sc; g_bias2[t] = bi; }
    else       { g_scale1[t] = sc; g_bias1[t] = bi; }
}

// ---------------- kernel 5: z = W2 @ relu(bn1(y1)) -> d_out; BN2 stats ----------------
__global__ __launch_bounds__(256) void gemmZ_kernel(const float* __restrict__ W2,
                                                    float* __restrict__ out) {
    int z = blockIdx.z, b = z >> 2, r = z & 3;
    int o0 = blockIdx.y * 128, n0 = blockIdx.x * 64;
    __shared__ union {
        struct { unsigned ws[16][136]; unsigned xs[16][72]; } mm;
        struct { float s[128]; float q[128]; } ep;
    } S;
    __shared__ float Ys[64][132];

    const float* y1z = g_y1 + (size_t)z * C_ * N_;
    int tid = threadIdx.x, lane = tid & 31, wp = tid >> 5;
    int wo = wp >> 1, wn = wp & 1, g = lane >> 2, t = lane & 3;
    int lwo = tid >> 2, lwk = (tid & 3) * 4;
    int xk = tid >> 4, xq = (tid & 15) * 4;

    float acc[2][4][4] = {};
    for (int c0 = 0; c0 < C_; c0 += 16) {
        float4 wv0 = *(const float4*)(W2 + (size_t)(o0 + lwo) * 256 + c0 + lwk);
        float4 wv1 = *(const float4*)(W2 + (size_t)(o0 + 64 + lwo) * 256 + c0 + lwk);
        float4 xv  = *(const float4*)(y1z + (size_t)(c0 + xk) * N_ + n0 + xq);
        float sc = g_scale1[c0 + xk], bi = g_bias1[c0 + xk];
        xv.x = fmaxf(fmaf(xv.x, sc, bi), 0.f); xv.y = fmaxf(fmaf(xv.y, sc, bi), 0.f);
        xv.z = fmaxf(fmaf(xv.z, sc, bi), 0.f); xv.w = fmaxf(fmaf(xv.w, sc, bi), 0.f);
        __syncthreads();
        S.mm.ws[lwk+0][lwo] = f2tf(wv0.x); S.mm.ws[lwk+1][lwo] = f2tf(wv0.y);
        S.mm.ws[lwk+2][lwo] = f2tf(wv0.z); S.mm.ws[lwk+3][lwo] = f2tf(wv0.w);
        S.mm.ws[lwk+0][64+lwo] = f2tf(wv1.x); S.mm.ws[lwk+1][64+lwo] = f2tf(wv1.y);
        S.mm.ws[lwk+2][64+lwo] = f2tf(wv1.z); S.mm.ws[lwk+3][64+lwo] = f2tf(wv1.w);
        uint4 xb = make_uint4(f2tf(xv.x), f2tf(xv.y), f2tf(xv.z), f2tf(xv.w));
        *(uint4*)&S.mm.xs[xk][xq] = xb;
        __syncthreads();
        #pragma unroll
        for (int ks = 0; ks < 16; ks += 8) {
            unsigned af[2][4], bf[4][2];
            #pragma unroll
            for (int mi = 0; mi < 2; mi++) {
                int ob = wo*32 + mi*16;
                af[mi][0] = S.mm.ws[ks+t][ob+g];   af[mi][1] = S.mm.ws[ks+t][ob+g+8];
                af[mi][2] = S.mm.ws[ks+t+4][ob+g]; af[mi][3] = S.mm.ws[ks+t+4][ob+g+8];
            }
            #pragma unroll
            for (int ni = 0; ni < 4; ni++) {
                int nb = wn*32 + ni*8;
                bf[ni][0] = S.mm.xs[ks+t][nb+g];   bf[ni][1] = S.mm.xs[ks+t+4][nb+g];
            }
            #pragma unroll
            for (int mi = 0; mi < 2; mi++)
                #pragma unroll
                for (int ni = 0; ni < 4; ni++)
                    mma8(acc[mi][ni], af[mi], bf[ni]);
        }
    }
    __syncthreads();
    #pragma unroll
    for (int mi = 0; mi < 2; mi++)
        #pragma unroll
        for (int ni = 0; ni < 4; ni++) {
            int orow = wo*32 + mi*16 + g;
            int ncol = wn*32 + ni*8 + 2*t;
            Ys[ncol  ][orow  ] = acc[mi][ni][0];
            Ys[ncol+1][orow  ] = acc[mi][ni][1];
            Ys[ncol  ][orow+8] = acc[mi][ni][2];
            Ys[ncol+1][orow+8] = acc[mi][ni][3];
        }
    if (tid < 128) { S.ep.s[tid] = 0.f; S.ep.q[tid] = 0.f; }
    __syncthreads();
    // BN2 stats + coalesced store to out[b][o][r][n]
    float* ob = out + (size_t)b * (256*NR_*N_) + (size_t)r * N_;
    int o = tid >> 1, hf = tid & 1;
    float ps = 0.f, pq = 0.f;
    #pragma unroll
    for (int j = 0; j < 8; j++) {
        int n = hf*32 + j*4;
        float4 v = make_float4(Ys[n][o], Ys[n+1][o], Ys[n+2][o], Ys[n+3][o]);
        ps += v.x + v.y + v.z + v.w;
        pq += v.x*v.x + v.y*v.y + v.z*v.z + v.w*v.w;
        *(float4*)(ob + (size_t)(o0 + o) * (NR_*N_) + n0 + n) = v;
    }
    atomicAdd(&S.ep.s[o], ps);
    atomicAdd(&S.ep.q[o], pq);
    __syncthreads();
    if (tid < 128) {
        atomicAdd(&g_s2[o0 + tid], S.ep.s[tid]);
        atomicAdd(&g_q2[o0 + tid], S.ep.q[tid]);
    }
}

// ---------------- kernel 7: in-place BN2 + ReLU on d_out ----------------
__global__ void out_kernel(float* __restrict__ out) {
    int i = blockIdx.x * blockDim.x + threadIdx.x;    // float4 index
    int o = (i >> 11) & 255;                          // (i*4 / 8192) % 256
    float sc = g_scale2[o], bi = g_bias2[o];
    float4 v = ((float4*)out)[i];
    v.x = fmaxf(fmaf(v.x, sc, bi), 0.f);
    v.y = fmaxf(fmaf(v.y, sc, bi), 0.f);
    v.z = fmaxf(fmaf(v.z, sc, bi), 0.f);
    v.w = fmaxf(fmaf(v.w, sc, bi), 0.f);
    ((float4*)out)[i] = v;
}

// ---------------- launch ----------------
extern "C" void kernel_launch(void* const* d_in, const int* in_sizes, int n_in,
                              void* d_out, int out_size) {
    const float* unknown = (const float*)d_in[0];
    const float* known   = (const float*)d_in[1];
    const float* uf      = (const float*)d_in[2];
    const float* kf      = (const float*)d_in[3];
    const float* W1      = (const float*)d_in[4];
    const float* g1      = (const float*)d_in[5];
    const float* b1      = (const float*)d_in[6];
    const float* W2      = (const float*)d_in[7];
    const float* g2      = (const float*)d_in[8];
    const float* b2      = (const float*)d_in[9];
    float* out = (float*)d_out;

    zero_stats_kernel<<<1, 256>>>();
    knn_kernel<<<dim3(N_/256, B_), 256>>>(unknown, known);
    gemmG_kernel<<<dim3(M_/64, C_/128, B_*NR_), 256>>>(kf, W1);
    gemmY1_kernel<<<dim3(N_/64, C_/128, B_*NR_), 256>>>(uf, W1);
    bnfin_kernel<<<1, 256>>>(g1, b1, 0);
    gemmZ_kernel<<<dim3(N_/64, C_/128, B_*NR_), 256>>>(W2, out);
    bnfin_kernel<<<1, 256>>>(g2, b2, 1);
    out_kernel<<<(B_*256*NR_*N_/4) / 256, 256>>>(out);
}

// round 5
// speedup vs baseline: 2.4472x; 1.0039x over previous
#include <cuda_runtime.h>
#include <math.h>

// Problem constants (fixed shapes from reference)
#define B_   8
#define N_   2048
#define M_   512
#define C_   256
#define NR_  4
#define CNT_ (B_*NR_*N_)      // 65536 elements per channel for BN stats

// ---------------- scratch (static device globals; no allocation) ----------------
__device__ float g_G [B_*NR_*M_*C_];   // [z=b*4+r][m][o]  16.8 MB
__device__ float g_y1[B_*NR_*C_*N_];   // [z][c][n]        67 MB
__device__ int   g_idx[B_*N_*3];
__device__ float g_w  [B_*N_*3];
__device__ float g_s1[C_], g_q1[C_], g_s2[C_], g_q2[C_];
__device__ float g_scale1[C_], g_bias1[C_], g_scale2[C_], g_bias2[C_];

// ---------------- tf32 helpers ----------------
__device__ __forceinline__ unsigned f2tf(float f) {
    unsigned u; asm("cvt.rna.tf32.f32 %0, %1;" : "=r"(u) : "f"(f)); return u;
}
__device__ __forceinline__ void mma8(float* c, const unsigned* a, const unsigned* b) {
    asm volatile("mma.sync.aligned.m16n8k8.row.col.f32.tf32.tf32.f32 "
        "{%0,%1,%2,%3}, {%4,%5,%6,%7}, {%8,%9}, {%0,%1,%2,%3};"
        : "+f"(c[0]), "+f"(c[1]), "+f"(c[2]), "+f"(c[3])
        : "r"(a[0]), "r"(a[1]), "r"(a[2]), "r"(a[3]), "r"(b[0]), "r"(b[1]));
}

// ---------------- kernel 0: zero BN accumulators (graph replays!) ----------------
__global__ void zero_stats_kernel() {
    int t = threadIdx.x;
    g_s1[t] = 0.f; g_q1[t] = 0.f; g_s2[t] = 0.f; g_q2[t] = 0.f;
}

// ---------------- kernel 1: 3-NN + inverse-distance weights ----------------
__global__ void knn_kernel(const float* __restrict__ unknown,
                           const float* __restrict__ known) {
    __shared__ float ks[M_*3];
    int b = blockIdx.y;
    const float* kb = known + (size_t)b * M_ * 3;
    for (int i = threadIdx.x; i < M_*3; i += blockDim.x) ks[i] = kb[i];
    __syncthreads();

    int n = blockIdx.x * blockDim.x + threadIdx.x;
    const float* u = unknown + ((size_t)b * N_ + n) * 3;
    float ux = u[0], uy = u[1], uz = u[2];

    float d0 = 3.4e38f, d1 = 3.4e38f, d2 = 3.4e38f;
    int   i0 = 0, i1 = 0, i2 = 0;
    for (int m = 0; m < M_; m++) {
        float dx = ux - ks[m*3], dy = uy - ks[m*3+1], dz = uz - ks[m*3+2];
        float d  = dx*dx + dy*dy + dz*dz;
        if (d < d2) {
            if (d < d0)      { d2=d1; i2=i1; d1=d0; i1=i0; d0=d; i0=m; }
            else if (d < d1) { d2=d1; i2=i1; d1=d;  i1=m; }
            else             { d2=d;  i2=m; }
        }
    }
    float r0 = 1.f / (sqrtf(fmaxf(d0, 0.f)) + 1e-8f);
    float r1 = 1.f / (sqrtf(fmaxf(d1, 0.f)) + 1e-8f);
    float r2 = 1.f / (sqrtf(fmaxf(d2, 0.f)) + 1e-8f);
    float inv = 1.f / (r0 + r1 + r2);
    int base = (b * N_ + n) * 3;
    g_idx[base] = i0; g_idx[base+1] = i1; g_idx[base+2] = i2;
    g_w[base] = r0*inv; g_w[base+1] = r1*inv; g_w[base+2] = r2*inv;
}

// ============================================================================
// tf32 MMA GEMM core: block tile 128 (o = mma-M) x 64 (n = mma-N), K chunk 16.
// 8 warps as (4 o) x (2 n); warp tile 32o x 32n = 2 mtiles x 4 ntiles m16n8k8.
// A = weights W[o][k] staged as ws[k][o] (pitch 136 -> conflict-free frag LDS).
// B = activations x[k][n] staged as xs[k][n] (pitch 72).
// Result staged to Ys[n][o] (pitch 132) for flexible epilogues.
// ============================================================================

// ---------------- kernel 2: G[z][m][o] = W1a @ kf ----------------
__global__ __launch_bounds__(256) void gemmG_kernel(const float* __restrict__ kf,
                                                    const float* __restrict__ W1) {
    int z = blockIdx.z, b = z >> 2, r = z & 3;
    int o0 = blockIdx.y * 128, n0 = blockIdx.x * 64;   // n == m dim here
    __shared__ unsigned ws[16][136];
    __shared__ unsigned xs[16][72];
    __shared__ float Ys[64][132];

    const float* kfb = kf + (size_t)b * (C_*NR_*M_) + (size_t)r * M_;
    int tid = threadIdx.x, lane = tid & 31, wp = tid >> 5;
    int wo = wp >> 1, wn = wp & 1, g = lane >> 2, t = lane & 3;
    int lwo = tid >> 2, lwk = (tid & 3) * 4;
    int xk = tid >> 4, xq = (tid & 15) * 4;

    float acc[2][4][4] = {};
    for (int c0 = 0; c0 < C_; c0 += 16) {
        float4 wv0 = *(const float4*)(W1 + (size_t)(o0 + lwo) * 512 + c0 + lwk);
        float4 wv1 = *(const float4*)(W1 + (size_t)(o0 + 64 + lwo) * 512 + c0 + lwk);
        float4 xv  = *(const float4*)(kfb + (size_t)(c0 + xk) * (NR_*M_) + n0 + xq);
        __syncthreads();
        ws[lwk+0][lwo] = f2tf(wv0.x); ws[lwk+1][lwo] = f2tf(wv0.y);
        ws[lwk+2][lwo] = f2tf(wv0.z); ws[lwk+3][lwo] = f2tf(wv0.w);
        ws[lwk+0][64+lwo] = f2tf(wv1.x); ws[lwk+1][64+lwo] = f2tf(wv1.y);
        ws[lwk+2][64+lwo] = f2tf(wv1.z); ws[lwk+3][64+lwo] = f2tf(wv1.w);
        uint4 xb = make_uint4(f2tf(xv.x), f2tf(xv.y), f2tf(xv.z), f2tf(xv.w));
        *(uint4*)&xs[xk][xq] = xb;
        __syncthreads();
        #pragma unroll
        for (int ks = 0; ks < 16; ks += 8) {
            unsigned af[2][4], bf[4][2];
            #pragma unroll
            for (int mi = 0; mi < 2; mi++) {
                int ob = wo*32 + mi*16;
                af[mi][0] = ws[ks+t][ob+g];   af[mi][1] = ws[ks+t][ob+g+8];
                af[mi][2] = ws[ks+t+4][ob+g]; af[mi][3] = ws[ks+t+4][ob+g+8];
            }
            #pragma unroll
            for (int ni = 0; ni < 4; ni++) {
                int nb = wn*32 + ni*8;
                bf[ni][0] = xs[ks+t][nb+g];   bf[ni][1] = xs[ks+t+4][nb+g];
            }
            #pragma unroll
            for (int mi = 0; mi < 2; mi++)
                #pragma unroll
                for (int ni = 0; ni < 4; ni++)
                    mma8(acc[mi][ni], af[mi], bf[ni]);
        }
    }
    __syncthreads();
    #pragma unroll
    for (int mi = 0; mi < 2; mi++)
        #pragma unroll
        for (int ni = 0; ni < 4; ni++) {
            int orow = wo*32 + mi*16 + g;
            int ncol = wn*32 + ni*8 + 2*t;
            Ys[ncol  ][orow  ] = acc[mi][ni][0];
            Ys[ncol+1][orow  ] = acc[mi][ni][1];
            Ys[ncol  ][orow+8] = acc[mi][ni][2];
            Ys[ncol+1][orow+8] = acc[mi][ni][3];
        }
    __syncthreads();
    // coalesced copy to G[z][m][o] (o contiguous, float4)
    float* Gz = g_G + (size_t)z * M_ * C_;
    int oq = tid & 31, nl0 = tid >> 5;
    #pragma unroll
    for (int it = 0; it < 8; it++) {
        int nl = nl0 + it*8;
        float4 v = *(float4*)&Ys[nl][oq*4];
        *(float4*)(Gz + (size_t)(n0 + nl) * C_ + o0 + oq*4) = v;
    }
}

// ---------------- kernel 3: y1 = W1b @ uf + gather(G, idx, w); BN1 stats ----------------
__global__ __launch_bounds__(256) void gemmY1_kernel(const float* __restrict__ uf,
                                                     const float* __restrict__ W1) {
    int z = blockIdx.z, b = z >> 2, r = z & 3;
    int o0 = blockIdx.y * 128, n0 = blockIdx.x * 64;
    __shared__ union {
        struct { unsigned ws[16][136]; unsigned xs[16][72]; } mm;
        struct { float w[192]; int idx[192]; float s[128]; float q[128]; } ep;
    } S;
    __shared__ float Ys[64][132];

    const float* ufb = uf + (size_t)b * (C_*NR_*N_) + (size_t)r * N_;
    int tid = threadIdx.x, lane = tid & 31, wp = tid >> 5;
    int wo = wp >> 1, wn = wp & 1, g = lane >> 2, t = lane & 3;
    int lwo = tid >> 2, lwk = (tid & 3) * 4;
    int xk = tid >> 4, xq = (tid & 15) * 4;

    float acc[2][4][4] = {};
    for (int c0 = 0; c0 < C_; c0 += 16) {
        float4 wv0 = *(const float4*)(W1 + (size_t)(o0 + lwo) * 512 + 256 + c0 + lwk);
        float4 wv1 = *(const float4*)(W1 + (size_t)(o0 + 64 + lwo) * 512 + 256 + c0 + lwk);
        float4 xv  = *(const float4*)(ufb + (size_t)(c0 + xk) * (NR_*N_) + n0 + xq);
        __syncthreads();
        S.mm.ws[lwk+0][lwo] = f2tf(wv0.x); S.mm.ws[lwk+1][lwo] = f2tf(wv0.y);
        S.mm.ws[lwk+2][lwo] = f2tf(wv0.z); S.mm.ws[lwk+3][lwo] = f2tf(wv0.w);
        S.mm.ws[lwk+0][64+lwo] = f2tf(wv1.x); S.mm.ws[lwk+1][64+lwo] = f2tf(wv1.y);
        S.mm.ws[lwk+2][64+lwo] = f2tf(wv1.z); S.mm.ws[lwk+3][64+lwo] = f2tf(wv1.w);
        uint4 xb = make_uint4(f2tf(xv.x), f2tf(xv.y), f2tf(xv.z), f2tf(xv.w));
        *(uint4*)&S.mm.xs[xk][xq] = xb;
        __syncthreads();
        #pragma unroll
        for (int ks = 0; ks < 16; ks += 8) {
            unsigned af[2][4], bf[4][2];
            #pragma unroll
            for (int mi = 0; mi < 2; mi++) {
                int ob = wo*32 + mi*16;
                af[mi][0] = S.mm.ws[ks+t][ob+g];   af[mi][1] = S.mm.ws[ks+t][ob+g+8];
                af[mi][2] = S.mm.ws[ks+t+4][ob+g]; af[mi][3] = S.mm.ws[ks+t+4][ob+g+8];
            }
            #pragma unroll
            for (int ni = 0; ni < 4; ni++) {
                int nb = wn*32 + ni*8;
                bf[ni][0] = S.mm.xs[ks+t][nb+g];   bf[ni][1] = S.mm.xs[ks+t+4][nb+g];
            }
            #pragma unroll
            for (int mi = 0; mi < 2; mi++)
                #pragma unroll
                for (int ni = 0; ni < 4; ni++)
                    mma8(acc[mi][ni], af[mi], bf[ni]);
        }
    }
    __syncthreads();  // ws/xs dead beyond here; ep union becomes live
    // stage accumulators
    #pragma unroll
    for (int mi = 0; mi < 2; mi++)
        #pragma unroll
        for (int ni = 0; ni < 4; ni++) {
            int orow = wo*32 + mi*16 + g;
            int ncol = wn*32 + ni*8 + 2*t;
            Ys[ncol  ][orow  ] = acc[mi][ni][0];
            Ys[ncol+1][orow  ] = acc[mi][ni][1];
            Ys[ncol  ][orow+8] = acc[mi][ni][2];
            Ys[ncol+1][orow+8] = acc[mi][ni][3];
        }
    // load interpolation weights/indices for this n-range; zero stats
    for (int l = tid; l < 192; l += 256) {
        S.ep.w[l]   = g_w  [(b * N_ + n0) * 3 + l];
        S.ep.idx[l] = g_idx[(b * N_ + n0) * 3 + l];
    }
    if (tid < 128) { S.ep.s[tid] = 0.f; S.ep.q[tid] = 0.f; }
    __syncthreads();
    // phase 2: gather epilogue, o-vectorized (G z-slice is L2-hot)
    const float* Gz = g_G + (size_t)z * M_ * C_;
    int oq = tid & 31, nl0 = tid >> 5;
    #pragma unroll
    for (int it = 0; it < 8; it++) {
        int nl = nl0 + it*8;
        float4 v = *(float4*)&Ys[nl][oq*4];
        float w0 = S.ep.w[nl*3], w1 = S.ep.w[nl*3+1], w2 = S.ep.w[nl*3+2];
        int   i0 = S.ep.idx[nl*3], i1 = S.ep.idx[nl*3+1], i2 = S.ep.idx[nl*3+2];
        float4 gA = *(const float4*)(Gz + (size_t)i0 * C_ + o0 + oq*4);
        float4 gB = *(const float4*)(Gz + (size_t)i1 * C_ + o0 + oq*4);
        float4 gC = *(const float4*)(Gz + (size_t)i2 * C_ + o0 + oq*4);
        v.x += w0*gA.x + w1*gB.x + w2*gC.x;
        v.y += w0*gA.y + w1*gB.y + w2*gC.y;
        v.z += w0*gA.z + w1*gB.z + w2*gC.z;
        v.w += w0*gA.w + w1*gB.w + w2*gC.w;
        *(float4*)&Ys[nl][oq*4] = v;
    }
    __syncthreads();
    // phase 3: BN1 stats + coalesced float4 store (n contiguous)
    float* y1z = g_y1 + (size_t)z * C_ * N_;
    int o = tid >> 1, hf = tid & 1;
    float ps = 0.f, pq = 0.f;
    #pragma unroll
    for (int j = 0; j < 8; j++) {
        int n = hf*32 + j*4;
        float4 v = make_float4(Ys[n][o], Ys[n+1][o], Ys[n+2][o], Ys[n+3][o]);
        ps += v.x + v.y + v.z + v.w;
        pq += v.x*v.x + v.y*v.y + v.z*v.z + v.w*v.w;
        *(float4*)(y1z + (size_t)(o0 + o) * N_ + n0 + n) = v;
    }
    atomicAdd(&S.ep.s[o], ps);
    atomicAdd(&S.ep.q[o], pq);
    __syncthreads();
    if (tid < 128) {
        atomicAdd(&g_s1[o0 + tid], S.ep.s[tid]);
        atomicAdd(&g_q1[o0 + tid], S.ep.q[tid]);
    }
}

// ---------------- kernel 4/6: BN finalize ----------------
__global__ void bnfin_kernel(const float* __restrict__ gamma,
                             const float* __restrict__ beta, int which) {
    int t = threadIdx.x;
    float s = which ? g_s2[t] : g_s1[t];
    float q = which ? g_q2[t] : g_q1[t];
    float mean = s * (1.f / CNT_);
    float var  = q * (1.f / CNT_) - mean * mean;
    float sc = gamma[t] * rsqrtf(var + 1e-5f);
    float bi = beta[t] - mean * sc;
    if (which) { g_scale2[t] = sc; g_bias2[t] = bi; }
    else       { g_scale1[t] = sc; g_bias1[t] = bi; }
}

// ---------------- kernel 5: z = W2 @ relu(bn1(y1)) -> d_out; BN2 stats ----------------
__global__ __launch_bounds__(256) void gemmZ_kernel(const float* __restrict__ W2,
                                                    float* __restrict__ out) {
    int z = blockIdx.z, b = z >> 2, r = z & 3;
    int o0 = blockIdx.y * 128, n0 = blockIdx.x * 64;
    __shared__ union {
        struct { unsigned ws[16][136]; unsigned xs[16][72]; } mm;
        struct { float s[128]; float q[128]; } ep;
    } S;
    __shared__ float Ys[64][132];

    const float* y1z = g_y1 + (size_t)z * C_ * N_;
    int tid = threadIdx.x, lane = tid & 31, wp = tid >> 5;
    int wo = wp >> 1, wn = wp & 1, g = lane >> 2, t = lane & 3;
    int lwo = tid >> 2, lwk = (tid & 3) * 4;
    int xk = tid >> 4, xq = (tid & 15) * 4;

    float acc[2][4][4] = {};
    for (int c0 = 0; c0 < C_; c0 += 16) {
        float4 wv0 = *(const float4*)(W2 + (size_t)(o0 + lwo) * 256 + c0 + lwk);
        float4 wv1 = *(const float4*)(W2 + (size_t)(o0 + 64 + lwo) * 256 + c0 + lwk);
        float4 xv  = *(const float4*)(y1z + (size_t)(c0 + xk) * N_ + n0 + xq);
        float sc = g_scale1[c0 + xk], bi = g_bias1[c0 + xk];
        xv.x = fmaxf(fmaf(xv.x, sc, bi), 0.f); xv.y = fmaxf(fmaf(xv.y, sc, bi), 0.f);
        xv.z = fmaxf(fmaf(xv.z, sc, bi), 0.f); xv.w = fmaxf(fmaf(xv.w, sc, bi), 0.f);
        __syncthreads();
        S.mm.ws[lwk+0][lwo] = f2tf(wv0.x); S.mm.ws[lwk+1][lwo] = f2tf(wv0.y);
        S.mm.ws[lwk+2][lwo] = f2tf(wv0.z); S.mm.ws[lwk+3][lwo] = f2tf(wv0.w);
        S.mm.ws[lwk+0][64+lwo] = f2tf(wv1.x); S.mm.ws[lwk+1][64+lwo] = f2tf(wv1.y);
        S.mm.ws[lwk+2][64+lwo] = f2tf(wv1.z); S.mm.ws[lwk+3][64+lwo] = f2tf(wv1.w);
        uint4 xb = make_uint4(f2tf(xv.x), f2tf(xv.y), f2tf(xv.z), f2tf(xv.w));
        *(uint4*)&S.mm.xs[xk][xq] = xb;
        __syncthreads();
        #pragma unroll
        for (int ks = 0; ks < 16; ks += 8) {
            unsigned af[2][4], bf[4][2];
            #pragma unroll
            for (int mi = 0; mi < 2; mi++) {
                int ob = wo*32 + mi*16;
                af[mi][0] = S.mm.ws[ks+t][ob+g];   af[mi][1] = S.mm.ws[ks+t][ob+g+8];
                af[mi][2] = S.mm.ws[ks+t+4][ob+g]; af[mi][3] = S.mm.ws[ks+t+4][ob+g+8];
            }
            #pragma unroll
            for (int ni = 0; ni < 4; ni++) {
                int nb = wn*32 + ni*8;
                bf[ni][0] = S.mm.xs[ks+t][nb+g];   bf[ni][1] = S.mm.xs[ks+t+4][nb+g];
            }
            #pragma unroll
            for (int mi = 0; mi < 2; mi++)
                #pragma unroll
                for (int ni = 0; ni < 4; ni++)
                    mma8(acc[mi][ni], af[mi], bf[ni]);
        }
    }
    __syncthreads();
    #pragma unroll
    for (int mi = 0; mi < 2; mi++)
        #pragma unroll
        for (int ni = 0; ni < 4; ni++) {
            int orow = wo*32 + mi*16 + g;
            int ncol = wn*32 + ni*8 + 2*t;
            Ys[ncol  ][orow  ] = acc[mi][ni][0];
            Ys[ncol+1][orow  ] = acc[mi][ni][1];
            Ys[ncol  ][orow+8] = acc[mi][ni][2];
            Ys[ncol+1][orow+8] = acc[mi][ni][3];
        }
    if (tid < 128) { S.ep.s[tid] = 0.f; S.ep.q[tid] = 0.f; }
    __syncthreads();
    // BN2 stats + coalesced store to out[b][o][r][n]
    float* ob = out + (size_t)b * (256*NR_*N_) + (size_t)r * N_;
    int o = tid >> 1, hf = tid & 1;
    float ps = 0.f, pq = 0.f;
    #pragma unroll
    for (int j = 0; j < 8; j++) {
        int n = hf*32 + j*4;
        float4 v = make_float4(Ys[n][o], Ys[n+1][o], Ys[n+2][o], Ys[n+3][o]);
        ps += v.x + v.y + v.z + v.w;
        pq += v.x*v.x + v.y*v.y + v.z*v.z + v.w*v.w;
        *(float4*)(ob + (size_t)(o0 + o) * (NR_*N_) + n0 + n) = v;
    }
    atomicAdd(&S.ep.s[o], ps);
    atomicAdd(&S.ep.q[o], pq);
    __syncthreads();
    if (tid < 128) {
        atomicAdd(&g_s2[o0 + tid], S.ep.s[tid]);
        atomicAdd(&g_q2[o0 + tid], S.ep.q[tid]);
    }
}

// ---------------- kernel 7: in-place BN2 + ReLU on d_out ----------------
__global__ void out_kernel(float* __restrict__ out) {
    int i = blockIdx.x * blockDim.x + threadIdx.x;    // float4 index
    int o = (i >> 11) & 255;                          // (i*4 / 8192) % 256
    float sc = g_scale2[o], bi = g_bias2[o];
    float4 v = ((float4*)out)[i];
    v.x = fmaxf(fmaf(v.x, sc, bi), 0.f);
    v.y = fmaxf(fmaf(v.y, sc, bi), 0.f);
    v.z = fmaxf(fmaf(v.z, sc, bi), 0.f);
    v.w = fmaxf(fmaf(v.w, sc, bi), 0.f);
    ((float4*)out)[i] = v;
}

// ---------------- launch ----------------
extern "C" void kernel_launch(void* const* d_in, const int* in_sizes, int n_in,
                              void* d_out, int out_size) {
    const float* unknown = (const float*)d_in[0];
    const float* known   = (const float*)d_in[1];
    const float* uf      = (const float*)d_in[2];
    const float* kf      = (const float*)d_in[3];
    const float* W1      = (const float*)d_in[4];
    const float* g1      = (const float*)d_in[5];
    const float* b1      = (const float*)d_in[6];
    const float* W2      = (const float*)d_in[7];
    const float* g2      = (const float*)d_in[8];
    const float* b2      = (const float*)d_in[9];
    float* out = (float*)d_out;

    zero_stats_kernel<<<1, 256>>>();
    knn_kernel<<<dim3(N_/256, B_), 256>>>(unknown, known);
    gemmG_kernel<<<dim3(M_/64, C_/128, B_*NR_), 256>>>(kf, W1);
    gemmY1_kernel<<<dim3(N_/64, C_/128, B_*NR_), 256>>>(uf, W1);
    bnfin_kernel<<<1, 256>>>(g1, b1, 0);
    gemmZ_kernel<<<dim3(N_/64, C_/128, B_*NR_), 256>>>(W2, out);
    bnfin_kernel<<<1, 256>>>(g2, b2, 1);
    out_kernel<<<(B_*256*NR_*N_/4) / 256, 256>>>(out);
}